// round 3
// baseline (speedup 1.0000x reference)
#include <cuda_runtime.h>
#include <math.h>

#define N_NODES 50000
#define N_EDGES 800000
#define NHEAD 8
#define D_OUT 32
#define D_IN 256
#define NH 256            // NHEAD * D_OUT
#define E_FEAT 64
#define N_ETYPES 5
#define NEG 0.2f
#define NB 196            // ceil(N_NODES / 256)

// ---------------- scratch (device globals; no allocation allowed) ----------------
__device__ float    g_h[N_NODES * NH];          // projected node features [N,8,32]
__device__ float    g_hl[N_NODES * NHEAD];
__device__ float    g_hr[N_NODES * NHEAD];
__device__ float    g_he[N_ETYPES * NHEAD];
__device__ float    g_att[N_EDGES * NHEAD];     // logits -> ex (in place)
__device__ unsigned g_m[N_NODES * NHEAD];       // segment max (order-preserving uint)
__device__ float    g_denom[N_NODES * NHEAD];
__device__ int      g_counts[N_NODES];
__device__ int      g_offs[N_NODES];
__device__ int      g_cursor[N_NODES];
__device__ int      g_perm[N_EDGES];
__device__ int      g_bsums[256];

// order-preserving float<->uint map for atomicMax on floats
__device__ __forceinline__ unsigned f_enc(float f) {
    unsigned u = __float_as_uint(f);
    return (u & 0x80000000u) ? ~u : (u | 0x80000000u);
}
__device__ __forceinline__ float f_dec(unsigned k) {
    return __uint_as_float((k & 0x80000000u) ? (k ^ 0x80000000u) : ~k);
}

// ---------------- init ----------------
__global__ void k_init() {
    int i = blockIdx.x * blockDim.x + threadIdx.x;
    if (i < N_NODES) g_counts[i] = 0;
    if (i < N_NODES * NHEAD) { g_m[i] = 0u; g_denom[i] = 0.f; }
}

// ---------------- GEMM: h = x @ W  (M=50000, N=256, K=256), fp32 SIMT ----------------
#define BM 128
#define BN 128
#define BK 8
__global__ __launch_bounds__(256, 2) void k_gemm(const float* __restrict__ X,
                                                 const float* __restrict__ W) {
    __shared__ float As[BK][132];     // padded stride for conflict-free transposed store
    __shared__ float Bs[BK][BN];
    int tid = threadIdx.x;
    int ty = tid >> 4, tx = tid & 15;
    int m0 = blockIdx.y * BM;
    int n0 = blockIdx.x * BN;

    float acc[8][8];
#pragma unroll
    for (int i = 0; i < 8; i++)
#pragma unroll
        for (int j = 0; j < 8; j++) acc[i][j] = 0.f;

    int lr = tid >> 1;          // A row within tile (0..127)
    int kq = tid & 1;           // which float4 in k (0..1)
    int bk = tid >> 5;          // B row (0..7)
    int bn = (tid & 31) * 4;    // B col
    bool arow_ok = (m0 + lr) < N_NODES;
    const float* xrow = X + (size_t)(m0 + lr) * D_IN + kq * 4;

    for (int k0 = 0; k0 < D_IN; k0 += BK) {
        float4 av = make_float4(0.f, 0.f, 0.f, 0.f);
        if (arow_ok) av = *(const float4*)(xrow + k0);
        As[kq * 4 + 0][lr] = av.x;
        As[kq * 4 + 1][lr] = av.y;
        As[kq * 4 + 2][lr] = av.z;
        As[kq * 4 + 3][lr] = av.w;
        float4 bv = *(const float4*)(W + (size_t)(k0 + bk) * NH + n0 + bn);
        *(float4*)&Bs[bk][bn] = bv;
        __syncthreads();
#pragma unroll
        for (int k = 0; k < BK; k++) {
            float4 a0 = *(const float4*)&As[k][ty * 8];
            float4 a1 = *(const float4*)&As[k][ty * 8 + 4];
            float4 b0 = *(const float4*)&Bs[k][tx * 8];
            float4 b1 = *(const float4*)&Bs[k][tx * 8 + 4];
            float a[8] = {a0.x, a0.y, a0.z, a0.w, a1.x, a1.y, a1.z, a1.w};
            float b[8] = {b0.x, b0.y, b0.z, b0.w, b1.x, b1.y, b1.z, b1.w};
#pragma unroll
            for (int i = 0; i < 8; i++)
#pragma unroll
                for (int j = 0; j < 8; j++) acc[i][j] = fmaf(a[i], b[j], acc[i][j]);
        }
        __syncthreads();
    }
#pragma unroll
    for (int i = 0; i < 8; i++) {
        int gm = m0 + ty * 8 + i;
        if (gm < N_NODES) {
#pragma unroll
            for (int j = 0; j < 8; j += 4) {
                float4 v;
                v.x = acc[i][j + 0]; v.y = acc[i][j + 1];
                v.z = acc[i][j + 2]; v.w = acc[i][j + 3];
                if (isnan(v.x)) v.x = 0.f;
                if (isnan(v.y)) v.y = 0.f;
                if (isnan(v.z)) v.z = 0.f;
                if (isnan(v.w)) v.w = 0.f;
                *(float4*)&g_h[(size_t)gm * NH + n0 + tx * 8 + j] = v;
            }
        }
    }
}

// ---------------- hl / hr: per-node attention dots ----------------
__global__ void k_hlhr(const float* __restrict__ a_l, const float* __restrict__ a_r) {
    int warp = threadIdx.x >> 5;
    int lane = threadIdx.x & 31;
    int n = blockIdx.x * 8 + warp;
    if (n >= N_NODES) return;
#pragma unroll
    for (int it = 0; it < 2; it++) {
        int off = it * 128 + lane * 4;
        int hd = off >> 5;
        int d0 = off & 31;
        float4 v  = *(const float4*)(g_h + (size_t)n * NH + off);
        float4 al = *(const float4*)(a_l + hd * D_OUT + d0);
        float4 ar = *(const float4*)(a_r + hd * D_OUT + d0);
        float pl = v.x * al.x + v.y * al.y + v.z * al.z + v.w * al.w;
        float pr = v.x * ar.x + v.y * ar.y + v.z * ar.z + v.w * ar.w;
#pragma unroll
        for (int o = 4; o >= 1; o >>= 1) {
            pl += __shfl_xor_sync(0xffffffffu, pl, o);
            pr += __shfl_xor_sync(0xffffffffu, pr, o);
        }
        if ((lane & 7) == 0) {
            g_hl[n * NHEAD + hd] = pl;
            g_hr[n * NHEAD + hd] = pr;
        }
    }
}

// ---------------- he: per-etype attention dots (tiny) ----------------
__global__ void k_he(const float* __restrict__ emb, const float* __restrict__ We,
                     const float* __restrict__ a_e) {
    int t = blockIdx.x >> 3, hd = blockIdx.x & 7;
    int f = threadIdx.x;   // 64 threads
    float ev = 0.f;
#pragma unroll 8
    for (int k = 0; k < E_FEAT; k++)
        ev += emb[t * E_FEAT + k] * We[k * (E_FEAT * NHEAD) + hd * E_FEAT + f];
    float s = ev * a_e[hd * E_FEAT + f];
#pragma unroll
    for (int o = 16; o >= 1; o >>= 1) s += __shfl_xor_sync(0xffffffffu, s, o);
    __shared__ float r2[2];
    if ((threadIdx.x & 31) == 0) r2[threadIdx.x >> 5] = s;
    __syncthreads();
    if (threadIdx.x == 0) g_he[t * NHEAD + hd] = r2[0] + r2[1];
}

// ---------------- CSR build over col ----------------
__global__ void k_hist(const int* __restrict__ col) {
    int e = blockIdx.x * blockDim.x + threadIdx.x;
    if (e < N_EDGES) atomicAdd(&g_counts[col[e]], 1);
}

__global__ void k_scanA() {
    int i = blockIdx.x * 256 + threadIdx.x;
    int v = (i < N_NODES) ? g_counts[i] : 0;
    int x = v;
    int lane = threadIdx.x & 31, wid = threadIdx.x >> 5;
#pragma unroll
    for (int o = 1; o < 32; o <<= 1) {
        int y = __shfl_up_sync(0xffffffffu, x, o);
        if (lane >= o) x += y;
    }
    __shared__ int ws[8];
    if (lane == 31) ws[wid] = x;
    __syncthreads();
    if (threadIdx.x == 0) {
        int s = 0;
        for (int w = 0; w < 8; w++) { int t = ws[w]; ws[w] = s; s += t; }
    }
    __syncthreads();
    int excl = x - v + ws[wid];
    if (i < N_NODES) g_offs[i] = excl;
    if (threadIdx.x == 255) g_bsums[blockIdx.x] = excl + v;
}

__global__ void k_scanB() {
    int i = threadIdx.x;
    int v = (i < NB) ? g_bsums[i] : 0;
    int x = v;
    int lane = threadIdx.x & 31, wid = threadIdx.x >> 5;
#pragma unroll
    for (int o = 1; o < 32; o <<= 1) {
        int y = __shfl_up_sync(0xffffffffu, x, o);
        if (lane >= o) x += y;
    }
    __shared__ int ws[8];
    if (lane == 31) ws[wid] = x;
    __syncthreads();
    if (threadIdx.x == 0) {
        int s = 0;
        for (int w = 0; w < 8; w++) { int t = ws[w]; ws[w] = s; s += t; }
    }
    __syncthreads();
    int excl = x - v + ws[wid];
    if (i < NB) g_bsums[i] = excl;
}

__global__ void k_scanC() {
    int i = blockIdx.x * 256 + threadIdx.x;
    if (i < N_NODES) {
        int o = g_offs[i] + g_bsums[blockIdx.x];
        g_offs[i] = o;
        g_cursor[i] = o;
    }
}

__global__ void k_scatter(const int* __restrict__ col) {
    int e = blockIdx.x * blockDim.x + threadIdx.x;
    if (e >= N_EDGES) return;
    int c = col[e];
    int pos = atomicAdd(&g_cursor[c], 1);
    g_perm[pos] = e;
}

// ---------------- per-edge logits + segment max ----------------
__global__ void k_logits(const int* __restrict__ row, const int* __restrict__ col,
                         const int* __restrict__ et) {
    int e = blockIdx.x * blockDim.x + threadIdx.x;
    if (e >= N_EDGES) return;
    int rr = row[e], cc = col[e], tt = et[e];
    const float4* hl4 = (const float4*)(g_hl + rr * NHEAD);
    const float4* hr4 = (const float4*)(g_hr + cc * NHEAD);
    const float4* he4 = (const float4*)(g_he + tt * NHEAD);
    float v[8];
#pragma unroll
    for (int q = 0; q < 2; q++) {
        float4 a = hl4[q], b = hr4[q], c = he4[q];
        float s;
        s = a.x + b.x + c.x; v[q * 4 + 0] = s > 0.f ? s : NEG * s;
        s = a.y + b.y + c.y; v[q * 4 + 1] = s > 0.f ? s : NEG * s;
        s = a.z + b.z + c.z; v[q * 4 + 2] = s > 0.f ? s : NEG * s;
        s = a.w + b.w + c.w; v[q * 4 + 3] = s > 0.f ? s : NEG * s;
    }
    *(float4*)(g_att + (size_t)e * 8 + 0) = make_float4(v[0], v[1], v[2], v[3]);
    *(float4*)(g_att + (size_t)e * 8 + 4) = make_float4(v[4], v[5], v[6], v[7]);
    unsigned* mp = g_m + cc * NHEAD;
#pragma unroll
    for (int i = 0; i < 8; i++) atomicMax(mp + i, f_enc(v[i]));
}

// ---------------- exp + segment sum ----------------
__global__ void k_exp(const int* __restrict__ col) {
    int e = blockIdx.x * blockDim.x + threadIdx.x;
    if (e >= N_EDGES) return;
    int cc = col[e];
    float* lp = g_att + (size_t)e * 8;
#pragma unroll
    for (int i = 0; i < 8; i++) {
        float mm = f_dec(g_m[cc * NHEAD + i]);
        float ex = expf(lp[i] - mm);
        lp[i] = ex;
        atomicAdd(&g_denom[cc * NHEAD + i], ex);
    }
}

// ---------------- attn output: ex / denom (write only to output slice) ----------------
__global__ void k_norm(const int* __restrict__ col, float* __restrict__ attn_out) {
    int e = blockIdx.x * blockDim.x + threadIdx.x;
    if (e >= N_EDGES) return;
    int cc = col[e];
    float4 e0 = *(const float4*)(g_att + (size_t)e * 8 + 0);
    float4 e1 = *(const float4*)(g_att + (size_t)e * 8 + 4);
    const float4* d4 = (const float4*)(g_denom + cc * NHEAD);
    float4 d0 = d4[0], d1 = d4[1];
    float4 a0 = make_float4(e0.x / d0.x, e0.y / d0.y, e0.z / d0.z, e0.w / d0.w);
    float4 a1 = make_float4(e1.x / d1.x, e1.y / d1.y, e1.z / d1.z, e1.w / d1.w);
    *(float4*)(attn_out + (size_t)e * 8 + 0) = a0;
    *(float4*)(attn_out + (size_t)e * 8 + 4) = a1;
}

// ---------------- CSR aggregation: out[n] = (1/denom) * sum_e ex * h[row] ----------------
__global__ __launch_bounds__(256) void k_agg(const int* __restrict__ row,
                                             float* __restrict__ out) {
    int n = blockIdx.x;
    int head = threadIdx.x >> 5;
    int lane = threadIdx.x & 31;
    int start = g_offs[n];
    int cnt = g_counts[n];
    float acc = 0.f;
    for (int base = 0; base < cnt; base += 32) {
        int m = min(cnt - base, 32);
        float a = 0.f;
        int r = 0;
        if (lane < m) {
            int e = g_perm[start + base + lane];
            a = g_att[(size_t)e * 8 + head];   // ex (unnormalized)
            r = row[e];
        }
        for (int jj = 0; jj < m; jj++) {
            float aj = __shfl_sync(0xffffffffu, a, jj);
            int rj = __shfl_sync(0xffffffffu, r, jj);
            acc = fmaf(aj, g_h[(size_t)rj * NH + head * D_OUT + lane], acc);
        }
    }
    float scale = (cnt > 0) ? (1.f / g_denom[n * NHEAD + head]) : 0.f;
    out[(size_t)n * NH + head * D_OUT + lane] = acc * scale;
}

// ---------------- launch ----------------
extern "C" void kernel_launch(void* const* d_in, const int* in_sizes, int n_in,
                              void* d_out, int out_size) {
    const float* x   = (const float*)d_in[0];
    const float* W   = (const float*)d_in[1];
    const float* We  = (const float*)d_in[2];
    const float* emb = (const float*)d_in[3];
    const float* a_l = (const float*)d_in[4];
    const float* a_r = (const float*)d_in[5];
    const float* a_e = (const float*)d_in[6];
    const int* row = (const int*)d_in[7];
    const int* col = (const int*)d_in[8];
    const int* et  = (const int*)d_in[9];
    float* out = (float*)d_out;
    float* attn_out = (out_size >= N_NODES * NH + N_EDGES * NHEAD)
                          ? (out + (size_t)N_NODES * NH)
                          : nullptr;

    const int EB = (N_EDGES + 255) / 256;

    k_init<<<(N_NODES * NHEAD + 255) / 256, 256>>>();

    dim3 ggrid(NH / BN, (N_NODES + BM - 1) / BM);
    k_gemm<<<ggrid, 256>>>(x, W);

    k_hlhr<<<(N_NODES + 7) / 8, 256>>>(a_l, a_r);
    k_he<<<N_ETYPES * NHEAD, 64>>>(emb, We, a_e);

    k_hist<<<EB, 256>>>(col);
    k_scanA<<<NB, 256>>>();
    k_scanB<<<1, 256>>>();
    k_scanC<<<NB, 256>>>();
    k_scatter<<<EB, 256>>>(col);

    k_logits<<<EB, 256>>>(row, col, et);
    k_exp<<<EB, 256>>>(col);
    if (attn_out) k_norm<<<EB, 256>>>(col, attn_out);
    k_agg<<<N_NODES, 256>>>(row, out);
}

// round 4
// speedup vs baseline: 1.0885x; 1.0885x over previous
#include <cuda_runtime.h>
#include <math.h>

#define N_NODES 50000
#define N_EDGES 800000
#define NHEAD 8
#define D_OUT 32
#define D_IN 256
#define NH 256            // NHEAD * D_OUT
#define E_FEAT 64
#define N_ETYPES 5
#define NEG 0.2f
#define NB 196            // ceil(N_NODES / 256)

// ---------------- scratch (device globals; no allocation allowed) ----------------
__device__ float    g_h[N_NODES * NH];          // projected node features [N,8,32]
__device__ float    g_hl[N_NODES * NHEAD];
__device__ float    g_hr[N_NODES * NHEAD];
__device__ float    g_he[N_ETYPES * NHEAD];
__device__ float    g_att[N_EDGES * NHEAD];     // logits -> ex (in place)
__device__ unsigned g_m[N_NODES * NHEAD];       // segment max (order-preserving uint)
__device__ float    g_denom[N_NODES * NHEAD];
__device__ int      g_counts[N_NODES];
__device__ int      g_offs[N_NODES];
__device__ int      g_cursor[N_NODES];
__device__ int      g_perm[N_EDGES];
__device__ int      g_rows[N_EDGES];            // row[] permuted into CSR order
__device__ int      g_bsums[256];

// order-preserving float<->uint map for atomicMax on floats
__device__ __forceinline__ unsigned f_enc(float f) {
    unsigned u = __float_as_uint(f);
    return (u & 0x80000000u) ? ~u : (u | 0x80000000u);
}
__device__ __forceinline__ float f_dec(unsigned k) {
    return __uint_as_float((k & 0x80000000u) ? (k ^ 0x80000000u) : ~k);
}

// ---------------- init ----------------
__global__ void k_init() {
    int i = blockIdx.x * blockDim.x + threadIdx.x;
    if (i < N_NODES) g_counts[i] = 0;
    if (i < N_NODES * NHEAD) { g_m[i] = 0u; g_denom[i] = 0.f; }
}

// ---------------- tf32 helpers ----------------
__device__ __forceinline__ unsigned cvt_tf32(float x) {
    unsigned r;
    asm("cvt.rna.tf32.f32 %0, %1;" : "=r"(r) : "f"(x));
    return r;
}
// split x into tf32 hi + tf32 lo (3xTF32 trick)
__device__ __forceinline__ void tf32_split(float x, unsigned& hi, unsigned& lo) {
    hi = cvt_tf32(x);
    lo = cvt_tf32(x - __uint_as_float(hi));
}
__device__ __forceinline__ void mma_tf32(float* d, const unsigned* a, const unsigned* b) {
    asm volatile(
        "mma.sync.aligned.m16n8k8.row.col.f32.tf32.tf32.f32 "
        "{%0,%1,%2,%3}, {%4,%5,%6,%7}, {%8,%9}, {%0,%1,%2,%3};"
        : "+f"(d[0]), "+f"(d[1]), "+f"(d[2]), "+f"(d[3])
        : "r"(a[0]), "r"(a[1]), "r"(a[2]), "r"(a[3]), "r"(b[0]), "r"(b[1]));
}

// ---------------- GEMM: h = x @ W via tensor cores (3xTF32, fp32-class accuracy) ----
// block = 8 warps as 4(m) x 2(n) -> 128 x 128 tile; warp tile 32 x 64 (2 x 8 mma tiles)
__global__ __launch_bounds__(256, 1) void k_gemm_tc(const float* __restrict__ X,
                                                    const float* __restrict__ W) {
    int warp = threadIdx.x >> 5, lane = threadIdx.x & 31;
    int gid = lane >> 2, tig = lane & 3;
    int wm = (warp >> 1) * 32;
    int wn = (warp & 1) * 64;
    int m0 = blockIdx.y * 128;
    int n0 = blockIdx.x * 128;

    float acc[2][8][4];
#pragma unroll
    for (int mt = 0; mt < 2; mt++)
#pragma unroll
        for (int nt = 0; nt < 8; nt++)
#pragma unroll
            for (int c = 0; c < 4; c++) acc[mt][nt][c] = 0.f;

    // precompute clamped row pointers (rows >= N_NODES read row 0; results discarded)
    size_t rp1[2], rp2[2];
#pragma unroll
    for (int mt = 0; mt < 2; mt++) {
        int r1 = m0 + wm + mt * 16 + gid;
        int r2 = r1 + 8;
        rp1[mt] = (size_t)(r1 < N_NODES ? r1 : 0) * D_IN;
        rp2[mt] = (size_t)(r2 < N_NODES ? r2 : 0) * D_IN;
    }

    for (int k0 = 0; k0 < D_IN; k0 += 8) {
        unsigned ah[2][4], al[2][4];
#pragma unroll
        for (int mt = 0; mt < 2; mt++) {
            float f0 = __ldg(X + rp1[mt] + k0 + tig);
            float f1 = __ldg(X + rp2[mt] + k0 + tig);
            float f2 = __ldg(X + rp1[mt] + k0 + tig + 4);
            float f3 = __ldg(X + rp2[mt] + k0 + tig + 4);
            tf32_split(f0, ah[mt][0], al[mt][0]);
            tf32_split(f1, ah[mt][1], al[mt][1]);
            tf32_split(f2, ah[mt][2], al[mt][2]);
            tf32_split(f3, ah[mt][3], al[mt][3]);
        }
#pragma unroll
        for (int nt = 0; nt < 8; nt++) {
            const float* wp = W + (size_t)(k0 + tig) * NH + n0 + wn + nt * 8 + gid;
            float g0 = __ldg(wp);
            float g1 = __ldg(wp + 4 * NH);
            unsigned bh[2], bl[2];
            tf32_split(g0, bh[0], bl[0]);
            tf32_split(g1, bh[1], bl[1]);
#pragma unroll
            for (int mt = 0; mt < 2; mt++) {
                mma_tf32(acc[mt][nt], ah[mt], bh);
                mma_tf32(acc[mt][nt], al[mt], bh);
                mma_tf32(acc[mt][nt], ah[mt], bl);
            }
        }
    }

    // store: c0,c1 -> row gid; c2,c3 -> row gid+8; cols 2*tig, 2*tig+1
#pragma unroll
    for (int mt = 0; mt < 2; mt++) {
        int r1 = m0 + wm + mt * 16 + gid;
        int r2 = r1 + 8;
#pragma unroll
        for (int nt = 0; nt < 8; nt++) {
            int c = n0 + wn + nt * 8 + 2 * tig;
            if (r1 < N_NODES)
                *(float2*)&g_h[(size_t)r1 * NH + c] = make_float2(acc[mt][nt][0], acc[mt][nt][1]);
            if (r2 < N_NODES)
                *(float2*)&g_h[(size_t)r2 * NH + c] = make_float2(acc[mt][nt][2], acc[mt][nt][3]);
        }
    }
}

// ---------------- hl / hr: per-node attention dots ----------------
__global__ void k_hlhr(const float* __restrict__ a_l, const float* __restrict__ a_r) {
    int warp = threadIdx.x >> 5;
    int lane = threadIdx.x & 31;
    int n = blockIdx.x * 8 + warp;
    if (n >= N_NODES) return;
#pragma unroll
    for (int it = 0; it < 2; it++) {
        int off = it * 128 + lane * 4;
        int hd = off >> 5;
        int d0 = off & 31;
        float4 v  = *(const float4*)(g_h + (size_t)n * NH + off);
        float4 al = *(const float4*)(a_l + hd * D_OUT + d0);
        float4 ar = *(const float4*)(a_r + hd * D_OUT + d0);
        float pl = v.x * al.x + v.y * al.y + v.z * al.z + v.w * al.w;
        float pr = v.x * ar.x + v.y * ar.y + v.z * ar.z + v.w * ar.w;
#pragma unroll
        for (int o = 4; o >= 1; o >>= 1) {
            pl += __shfl_xor_sync(0xffffffffu, pl, o);
            pr += __shfl_xor_sync(0xffffffffu, pr, o);
        }
        if ((lane & 7) == 0) {
            g_hl[n * NHEAD + hd] = pl;
            g_hr[n * NHEAD + hd] = pr;
        }
    }
}

// ---------------- he: per-etype attention dots (tiny) ----------------
__global__ void k_he(const float* __restrict__ emb, const float* __restrict__ We,
                     const float* __restrict__ a_e) {
    int t = blockIdx.x >> 3, hd = blockIdx.x & 7;
    int f = threadIdx.x;   // 64 threads
    float ev = 0.f;
#pragma unroll 8
    for (int k = 0; k < E_FEAT; k++)
        ev += emb[t * E_FEAT + k] * We[k * (E_FEAT * NHEAD) + hd * E_FEAT + f];
    float s = ev * a_e[hd * E_FEAT + f];
#pragma unroll
    for (int o = 16; o >= 1; o >>= 1) s += __shfl_xor_sync(0xffffffffu, s, o);
    __shared__ float r2[2];
    if ((threadIdx.x & 31) == 0) r2[threadIdx.x >> 5] = s;
    __syncthreads();
    if (threadIdx.x == 0) g_he[t * NHEAD + hd] = r2[0] + r2[1];
}

// ---------------- per-edge logits + segment max + histogram (fused) ----------------
__global__ void k_logits(const int* __restrict__ row, const int* __restrict__ col,
                         const int* __restrict__ et) {
    int e = blockIdx.x * blockDim.x + threadIdx.x;
    if (e >= N_EDGES) return;
    int rr = row[e], cc = col[e], tt = et[e];
    atomicAdd(&g_counts[cc], 1);
    const float4* hl4 = (const float4*)(g_hl + rr * NHEAD);
    const float4* hr4 = (const float4*)(g_hr + cc * NHEAD);
    const float4* he4 = (const float4*)(g_he + tt * NHEAD);
    float v[8];
#pragma unroll
    for (int q = 0; q < 2; q++) {
        float4 a = hl4[q], b = hr4[q], c = he4[q];
        float s;
        s = a.x + b.x + c.x; v[q * 4 + 0] = s > 0.f ? s : NEG * s;
        s = a.y + b.y + c.y; v[q * 4 + 1] = s > 0.f ? s : NEG * s;
        s = a.z + b.z + c.z; v[q * 4 + 2] = s > 0.f ? s : NEG * s;
        s = a.w + b.w + c.w; v[q * 4 + 3] = s > 0.f ? s : NEG * s;
    }
    *(float4*)(g_att + (size_t)e * 8 + 0) = make_float4(v[0], v[1], v[2], v[3]);
    *(float4*)(g_att + (size_t)e * 8 + 4) = make_float4(v[4], v[5], v[6], v[7]);
    unsigned* mp = g_m + cc * NHEAD;
#pragma unroll
    for (int i = 0; i < 8; i++) atomicMax(mp + i, f_enc(v[i]));
}

// ---------------- scans (CSR offsets over col histogram) ----------------
__global__ void k_scanA() {
    int i = blockIdx.x * 256 + threadIdx.x;
    int v = (i < N_NODES) ? g_counts[i] : 0;
    int x = v;
    int lane = threadIdx.x & 31, wid = threadIdx.x >> 5;
#pragma unroll
    for (int o = 1; o < 32; o <<= 1) {
        int y = __shfl_up_sync(0xffffffffu, x, o);
        if (lane >= o) x += y;
    }
    __shared__ int ws[8];
    if (lane == 31) ws[wid] = x;
    __syncthreads();
    if (threadIdx.x == 0) {
        int s = 0;
        for (int w = 0; w < 8; w++) { int t = ws[w]; ws[w] = s; s += t; }
    }
    __syncthreads();
    int excl = x - v + ws[wid];
    if (i < N_NODES) g_offs[i] = excl;
    if (threadIdx.x == 255) g_bsums[blockIdx.x] = excl + v;
}

__global__ void k_scanB() {
    int i = threadIdx.x;
    int v = (i < NB) ? g_bsums[i] : 0;
    int x = v;
    int lane = threadIdx.x & 31, wid = threadIdx.x >> 5;
#pragma unroll
    for (int o = 1; o < 32; o <<= 1) {
        int y = __shfl_up_sync(0xffffffffu, x, o);
        if (lane >= o) x += y;
    }
    __shared__ int ws[8];
    if (lane == 31) ws[wid] = x;
    __syncthreads();
    if (threadIdx.x == 0) {
        int s = 0;
        for (int w = 0; w < 8; w++) { int t = ws[w]; ws[w] = s; s += t; }
    }
    __syncthreads();
    int excl = x - v + ws[wid];
    if (i < NB) g_bsums[i] = excl;
}

__global__ void k_scanC() {
    int i = blockIdx.x * 256 + threadIdx.x;
    if (i < N_NODES) {
        int o = g_offs[i] + g_bsums[blockIdx.x];
        g_offs[i] = o;
        g_cursor[i] = o;
    }
}

// ---------------- fused: CSR scatter + exp + segment-sum ----------------
__global__ void k_scatter_exp(const int* __restrict__ row, const int* __restrict__ col) {
    int e = blockIdx.x * blockDim.x + threadIdx.x;
    if (e >= N_EDGES) return;
    int cc = col[e];
    int pos = atomicAdd(&g_cursor[cc], 1);
    g_perm[pos] = e;
    g_rows[pos] = row[e];
    float* lp = g_att + (size_t)e * 8;
    const unsigned* mp = g_m + cc * NHEAD;
    float* dp = g_denom + cc * NHEAD;
#pragma unroll
    for (int i = 0; i < 8; i++) {
        float ex = expf(lp[i] - f_dec(mp[i]));
        lp[i] = ex;
        atomicAdd(dp + i, ex);
    }
}

// ---------------- attn output: ex / denom (write only to output slice) ----------------
__global__ void k_norm(const int* __restrict__ col, float* __restrict__ attn_out) {
    int e = blockIdx.x * blockDim.x + threadIdx.x;
    if (e >= N_EDGES) return;
    int cc = col[e];
    float4 e0 = *(const float4*)(g_att + (size_t)e * 8 + 0);
    float4 e1 = *(const float4*)(g_att + (size_t)e * 8 + 4);
    const float4* d4 = (const float4*)(g_denom + cc * NHEAD);
    float4 d0 = d4[0], d1 = d4[1];
    float4 a0 = make_float4(e0.x / d0.x, e0.y / d0.y, e0.z / d0.z, e0.w / d0.w);
    float4 a1 = make_float4(e1.x / d1.x, e1.y / d1.y, e1.z / d1.z, e1.w / d1.w);
    *(float4*)(attn_out + (size_t)e * 8 + 0) = a0;
    *(float4*)(attn_out + (size_t)e * 8 + 4) = a1;
}

// ---------------- CSR aggregation: out[n] = (1/denom) * sum_e ex * h[row] ----------------
__global__ __launch_bounds__(256) void k_agg(float* __restrict__ out) {
    int n = blockIdx.x;
    int head = threadIdx.x >> 5;
    int lane = threadIdx.x & 31;
    int start = g_offs[n];
    int cnt = g_counts[n];
    float acc = 0.f;
    for (int base = 0; base < cnt; base += 32) {
        int m = min(cnt - base, 32);
        float a = 0.f;
        int r = 0;
        if (lane < m) {
            int e = g_perm[start + base + lane];
            a = g_att[(size_t)e * 8 + head];   // ex (unnormalized)
            r = g_rows[start + base + lane];
        }
        for (int jj = 0; jj < m; jj++) {
            float aj = __shfl_sync(0xffffffffu, a, jj);
            int rj = __shfl_sync(0xffffffffu, r, jj);
            acc = fmaf(aj, g_h[(size_t)rj * NH + head * D_OUT + lane], acc);
        }
    }
    float scale = (cnt > 0) ? (1.f / g_denom[n * NHEAD + head]) : 0.f;
    out[(size_t)n * NH + head * D_OUT + lane] = acc * scale;
}

// ---------------- launch ----------------
extern "C" void kernel_launch(void* const* d_in, const int* in_sizes, int n_in,
                              void* d_out, int out_size) {
    const float* x   = (const float*)d_in[0];
    const float* W   = (const float*)d_in[1];
    const float* We  = (const float*)d_in[2];
    const float* emb = (const float*)d_in[3];
    const float* a_l = (const float*)d_in[4];
    const float* a_r = (const float*)d_in[5];
    const float* a_e = (const float*)d_in[6];
    const int* row = (const int*)d_in[7];
    const int* col = (const int*)d_in[8];
    const int* et  = (const int*)d_in[9];
    float* out = (float*)d_out;
    float* attn_out = (out_size >= N_NODES * NH + N_EDGES * NHEAD)
                          ? (out + (size_t)N_NODES * NH)
                          : nullptr;

    const int EB = (N_EDGES + 255) / 256;

    k_init<<<(N_NODES * NHEAD + 255) / 256, 256>>>();

    dim3 ggrid(NH / 128, (N_NODES + 127) / 128);
    k_gemm_tc<<<ggrid, 256>>>(x, W);

    k_hlhr<<<(N_NODES + 7) / 8, 256>>>(a_l, a_r);
    k_he<<<N_ETYPES * NHEAD, 64>>>(emb, We, a_e);

    k_logits<<<EB, 256>>>(row, col, et);
    k_scanA<<<NB, 256>>>();
    k_scanB<<<1, 256>>>();
    k_scanC<<<NB, 256>>>();
    k_scatter_exp<<<EB, 256>>>(row, col);

    if (attn_out) k_norm<<<EB, 256>>>(col, attn_out);
    k_agg<<<N_NODES, 256>>>(out);
}